// round 1
// baseline (speedup 1.0000x reference)
#include <cuda_runtime.h>
#include <cstdint>

#define N_NODES 20000
#define N_EDGES 640000
#define MUL 32
#define ATTR 8
#define RB 16
#define FH 64

#define INV_M      0.17677669529663687f   // 1/sqrt(32)
#define INV_RB     0.25f                  // 1/sqrt(16)
#define INV_FH     0.125f                 // 1/sqrt(64)
#define INV_SQRT3  0.5773502691896258f
#define INV_DEG    0.17677669529663687f   // 1/sqrt(32)
#define INV_2M     0.125f                 // 1/sqrt(64)
#define INV_FAN    0.0625f                // 1/sqrt(256)
#define LOG2F_     0.6931471805599453f

// Scratch (device globals; no runtime allocation allowed)
__device__ float g_s[N_NODES * MUL];            // linear_1 scalar out   [N][32]
__device__ float g_v[N_NODES * MUL * 3];        // linear_1 vector out   [N][32][3]
__device__ float g_agg[N_NODES * MUL * 8];      // packed aggregation    [N][32][8]
// slot layout per (node,u): {s0, s1, v0x, v0y, v0z, v1x, v1y, v1z}
//   s0 = path w1 (0e x 0e),  s1 = path w4 (1o x 1o)
//   v0 = path w2 (0e x 1o),  v1 = path w3 (1o x 0e)

__device__ __forceinline__ float sspf(float x) {
    // softplus(x) - log(2), numerically stable
    return fmaxf(x, 0.0f) + log1pf(__expf(-fabsf(x))) - LOG2F_;
}

__device__ __forceinline__ void red_add_v4(float* addr, float a, float b, float c, float d) {
    asm volatile("red.global.add.v4.f32 [%0], {%1,%2,%3,%4};"
                 :: "l"(addr), "f"(a), "f"(b), "f"(c), "f"(d) : "memory");
}

// ---------------------------------------------------------------------------
// Kernel 0: zero the aggregation buffer
// ---------------------------------------------------------------------------
__global__ void k_zero() {
    int i = blockIdx.x * blockDim.x + threadIdx.x;        // 5000 * 256 threads
    float4* p = reinterpret_cast<float4*>(g_agg);
    p[i] = make_float4(0.f, 0.f, 0.f, 0.f);               // exactly N*256/4 float4s
}

// ---------------------------------------------------------------------------
// Kernel 1: linear_1  (per-node channel mixing, /sqrt(MUL))
// 2 threads per node, each owns 16 output channels.
// ---------------------------------------------------------------------------
__global__ void k_lin1(const float* __restrict__ node_s,
                       const float* __restrict__ node_v,
                       const float* __restrict__ W1s,
                       const float* __restrict__ W1v) {
    __shared__ float sW1s[32 * 32];
    __shared__ float sW1v[32 * 32];
    int tid = threadIdx.x;
    for (int i = tid; i < 1024; i += 256) {
        sW1s[i] = W1s[i] * INV_M;
        sW1v[i] = W1v[i] * INV_M;
    }
    __syncthreads();

    int gt = blockIdx.x * 256 + tid;
    int node = gt >> 1;
    int h = gt & 1;                                       // half: w in [h*16, h*16+16)
    if (node >= N_NODES) return;

    float accs[16];
    float accv[16][3];
#pragma unroll
    for (int w = 0; w < 16; w++) { accs[w] = 0.f; accv[w][0] = accv[w][1] = accv[w][2] = 0.f; }

    const float* srow = node_s + node * 32;
    const float* vrow = node_v + node * 96;
    for (int u = 0; u < 32; u++) {
        float su = srow[u];
        float vx = vrow[u * 3 + 0], vy = vrow[u * 3 + 1], vz = vrow[u * 3 + 2];
        const float* ws = &sW1s[u * 32 + h * 16];
        const float* wv = &sW1v[u * 32 + h * 16];
#pragma unroll
        for (int w = 0; w < 16; w++) {
            accs[w]    += su * ws[w];
            accv[w][0] += vx * wv[w];
            accv[w][1] += vy * wv[w];
            accv[w][2] += vz * wv[w];
        }
    }
    float* so = g_s + node * 32 + h * 16;
    float* vo = g_v + node * 96 + h * 48;
#pragma unroll
    for (int w = 0; w < 16; w++) {
        so[w] = accs[w];
        vo[w * 3 + 0] = accv[w][0];
        vo[w * 3 + 1] = accv[w][1];
        vo[w * 3 + 2] = accv[w][2];
    }
}

// ---------------------------------------------------------------------------
// Kernel 2: edge kernel — radial MLP + CG tensor product + scatter
// 128 edges/block, 256 threads. E = 640000 = 5000 * 128 exactly.
// Shared layout (floats): Wr1[16*64] | Wr2[64*128] | emb[128*17 pad] | h[64*128]
// ---------------------------------------------------------------------------
#define ET 128
#define EDGE_SMEM_FLOATS (1024 + 8192 + 128 * 17 + 8192)

__global__ void k_edge(const float* __restrict__ emb,
                       const float* __restrict__ y0,
                       const float* __restrict__ y1,
                       const int*   __restrict__ eidx,
                       const float* __restrict__ Wr1,
                       const float* __restrict__ Wr2) {
    extern __shared__ float sm[];
    float* sWr1 = sm;                       // [16][64], scaled by 1/sqrt(RB)
    float* sWr2 = sWr1 + 1024;              // [64][128], scaled by 1/sqrt(FH)
    float* semb = sWr2 + 8192;              // [128][17] padded
    float* sh   = semb + 128 * 17;          // [64][128], float4-addressed as [64][32]

    int tid = threadIdx.x;
    int e0 = blockIdx.x * ET;

    for (int i = tid; i < 1024; i += 256) sWr1[i] = Wr1[i] * INV_RB;
    for (int i = tid; i < 8192; i += 256) sWr2[i] = Wr2[i] * INV_FH;
    for (int i = tid; i < ET * RB; i += 256) {
        int e = i >> 4, k = i & 15;
        semb[e * 17 + k] = emb[e0 * RB + i];
    }
    __syncthreads();

    int te = tid & 31;     // edge group: edges te*4 .. te*4+3
    int th = tid >> 5;     // 0..7

    // ---- GEMM1: h[e][hh] = ssp( emb[e] . Wr1[:,hh] ), hh = th*8 + m ----
    float acc1[4][8];
#pragma unroll
    for (int j = 0; j < 4; j++)
#pragma unroll
        for (int m = 0; m < 8; m++) acc1[j][m] = 0.f;

    for (int k = 0; k < 16; k++) {
        float em[4];
#pragma unroll
        for (int j = 0; j < 4; j++) em[j] = semb[(te * 4 + j) * 17 + k];
        float wr[8];
#pragma unroll
        for (int m = 0; m < 8; m++) wr[m] = sWr1[k * 64 + th * 8 + m];
#pragma unroll
        for (int j = 0; j < 4; j++)
#pragma unroll
            for (int m = 0; m < 8; m++) acc1[j][m] += em[j] * wr[m];
    }
    // store ssp(h) to shared, float4 per (hh, edge-group)
    float4* sh4 = reinterpret_cast<float4*>(sh);
#pragma unroll
    for (int m = 0; m < 8; m++) {
        float4 hv;
        hv.x = sspf(acc1[0][m]);
        hv.y = sspf(acc1[1][m]);
        hv.z = sspf(acc1[2][m]);
        hv.w = sspf(acc1[3][m]);
        sh4[(th * 8 + m) * 32 + te] = hv;
    }
    __syncthreads();

    // ---- GEMM2: w[e][o], o = to + 8*jj (jj = p*4 + uu -> path p, u = to + 8*uu)
    int to = th;
    float acc[4][16];
#pragma unroll
    for (int j = 0; j < 4; j++)
#pragma unroll
        for (int jj = 0; jj < 16; jj++) acc[j][jj] = 0.f;

    for (int k = 0; k < 64; k++) {
        float4 h4 = sh4[k * 32 + te];
#pragma unroll
        for (int jj = 0; jj < 16; jj++) {
            float wv = sWr2[k * 128 + to + 8 * jj];       // warp-broadcast
            acc[0][jj] += h4.x * wv;
            acc[1][jj] += h4.y * wv;
            acc[2][jj] += h4.z * wv;
            acc[3][jj] += h4.w * wv;
        }
    }

    // ---- CG tensor product + vector-atomic scatter ----
#pragma unroll
    for (int j = 0; j < 4; j++) {
        int e = e0 + te * 4 + j;
        int src = eidx[e];
        int dst = eidx[N_EDGES + e];
        float yy0 = y0[e];
        float y1x = y1[e * 3 + 0], y1y = y1[e * 3 + 1], y1z = y1[e * 3 + 2];
        const float* sp = g_s + src * 32;
        const float* vp = g_v + src * 96;
        float* ap = g_agg + (size_t)dst * 256;
#pragma unroll
        for (int uu = 0; uu < 4; uu++) {
            int u = to + 8 * uu;
            float w1 = acc[j][0 + uu];
            float w2 = acc[j][4 + uu];
            float w3 = acc[j][8 + uu];
            float w4 = acc[j][12 + uu];
            float se = sp[u];
            float vx = vp[u * 3 + 0], vy = vp[u * 3 + 1], vz = vp[u * 3 + 2];

            float s0 = w1 * se * yy0 * INV_DEG;
            float s1 = w4 * (vx * y1x + vy * y1y + vz * y1z) * (INV_SQRT3 * INV_DEG);
            float a  = w2 * se * INV_DEG;
            float v0x = a * y1x, v0y = a * y1y, v0z = a * y1z;
            float b  = w3 * yy0 * INV_DEG;
            float v1x = b * vx, v1y = b * vy, v1z = b * vz;

            float* q = ap + u * 8;
            red_add_v4(q,     s0,  s1,  v0x, v0y);
            red_add_v4(q + 4, v0z, v1x, v1y, v1z);
        }
    }
}

// ---------------------------------------------------------------------------
// Kernel 3: linear_2 + self-connection + output
// 2 threads/node, 128 nodes/block. Weights in smem (scaled).
// Shared: W2s[64*32] | W2v[64*32] | Wscs[32*8*32] | Wscv[32*8*32] = 20480 floats
// ---------------------------------------------------------------------------
#define OUT_SMEM_FLOATS (2048 + 2048 + 8192 + 8192)

__global__ void k_out(const float* __restrict__ node_s,
                      const float* __restrict__ node_v,
                      const float* __restrict__ attrs,
                      const float* __restrict__ W2s,
                      const float* __restrict__ W2v,
                      const float* __restrict__ Wscs,
                      const float* __restrict__ Wscv,
                      float* __restrict__ out) {
    extern __shared__ float sm[];
    float* sW2s  = sm;                  // [64][32] * INV_2M
    float* sW2v  = sW2s + 2048;         // [64][32] * INV_2M
    float* sWscs = sW2v + 2048;         // [32*8][32] * INV_FAN
    float* sWscv = sWscs + 8192;        // [32*8][32] * INV_FAN

    int tid = threadIdx.x;
    for (int i = tid; i < 2048; i += 256) { sW2s[i]  = W2s[i]  * INV_2M;  sW2v[i]  = W2v[i]  * INV_2M; }
    for (int i = tid; i < 8192; i += 256) { sWscs[i] = Wscs[i] * INV_FAN; sWscv[i] = Wscv[i] * INV_FAN; }
    __syncthreads();

    int node = blockIdx.x * 128 + (tid >> 1);
    int h = tid & 1;
    if (node >= N_NODES) return;

    float accs[16];
    float accv[16][3];
#pragma unroll
    for (int w = 0; w < 16; w++) { accs[w] = 0.f; accv[w][0] = accv[w][1] = accv[w][2] = 0.f; }

    // ---- linear_2 on aggregated messages ----
    const float4* ag = reinterpret_cast<const float4*>(g_agg + (size_t)node * 256);
    for (int u = 0; u < 32; u++) {
        float4 A = ag[u * 2 + 0];   // {s0, s1, v0x, v0y}
        float4 B = ag[u * 2 + 1];   // {v0z, v1x, v1y, v1z}

        // k = u  (paths w1 / w2)
        {
            const float* rs = sW2s + u * 32 + h * 16;
            const float* rv = sW2v + u * 32 + h * 16;
            float as = A.x;
            float avx = A.z, avy = A.w, avz = B.x;
#pragma unroll
            for (int w = 0; w < 16; w++) {
                accs[w]    += as  * rs[w];
                accv[w][0] += avx * rv[w];
                accv[w][1] += avy * rv[w];
                accv[w][2] += avz * rv[w];
            }
        }
        // k = 32+u  (paths w4 / w3)
        {
            const float* rs = sW2s + (32 + u) * 32 + h * 16;
            const float* rv = sW2v + (32 + u) * 32 + h * 16;
            float as = A.y;
            float avx = B.y, avy = B.z, avz = B.w;
#pragma unroll
            for (int w = 0; w < 16; w++) {
                accs[w]    += as  * rs[w];
                accv[w][0] += avx * rv[w];
                accv[w][1] += avy * rv[w];
                accv[w][2] += avz * rv[w];
            }
        }
    }

    // ---- self connection (FullyConnectedTensorProduct with node attrs) ----
    float at[8];
    const float* arow = attrs + node * 8;
#pragma unroll
    for (int v = 0; v < 8; v++) at[v] = arow[v];

    const float* srow = node_s + node * 32;
    const float* vrow = node_v + node * 96;
    for (int u = 0; u < 32; u++) {
        float su = srow[u];
        float vx = vrow[u * 3 + 0], vy = vrow[u * 3 + 1], vz = vrow[u * 3 + 2];
#pragma unroll
        for (int v = 0; v < 8; v++) {
            float c  = su * at[v];
            float cx = vx * at[v], cy = vy * at[v], cz = vz * at[v];
            const float* ps = sWscs + (u * 8 + v) * 32 + h * 16;
            const float* pv = sWscv + (u * 8 + v) * 32 + h * 16;
#pragma unroll
            for (int w = 0; w < 16; w++) {
                float wcs = ps[w];
                float wcv = pv[w];
                accs[w]    += c  * wcs;
                accv[w][0] += cx * wcv;
                accv[w][1] += cy * wcv;
                accv[w][2] += cz * wcv;
            }
        }
    }

    // ---- write output: [out_s(32) | out_v(96 = w*3+i)] ----
    float* o = out + (size_t)node * 128;
#pragma unroll
    for (int w = 0; w < 16; w++) {
        int wg = h * 16 + w;
        o[wg] = accs[w];
        o[32 + wg * 3 + 0] = accv[w][0];
        o[32 + wg * 3 + 1] = accv[w][1];
        o[32 + wg * 3 + 2] = accv[w][2];
    }
}

// ---------------------------------------------------------------------------
extern "C" void kernel_launch(void* const* d_in, const int* in_sizes, int n_in,
                              void* d_out, int out_size) {
    const float* node_s     = (const float*)d_in[0];
    const float* node_v     = (const float*)d_in[1];
    const float* node_attrs = (const float*)d_in[2];
    const float* edge_emb   = (const float*)d_in[3];
    const float* edge_y0    = (const float*)d_in[4];
    const float* edge_y1    = (const float*)d_in[5];
    const int*   edge_index = (const int*)d_in[6];
    const float* W1s        = (const float*)d_in[7];
    const float* W1v        = (const float*)d_in[8];
    const float* Wr1        = (const float*)d_in[9];
    const float* Wr2        = (const float*)d_in[10];
    const float* W2s        = (const float*)d_in[11];
    const float* W2v        = (const float*)d_in[12];
    const float* Wscs       = (const float*)d_in[13];
    const float* Wscv       = (const float*)d_in[14];
    float* out = (float*)d_out;

    cudaFuncSetAttribute(k_edge, cudaFuncAttributeMaxDynamicSharedMemorySize,
                         EDGE_SMEM_FLOATS * sizeof(float));
    cudaFuncSetAttribute(k_out, cudaFuncAttributeMaxDynamicSharedMemorySize,
                         OUT_SMEM_FLOATS * sizeof(float));

    // zero agg: N_NODES*256 floats = 1,280,000 float4s = 5000 blocks * 256
    k_zero<<<5000, 256>>>();
    k_lin1<<<(2 * N_NODES + 255) / 256, 256>>>(node_s, node_v, W1s, W1v);
    k_edge<<<N_EDGES / ET, 256, EDGE_SMEM_FLOATS * sizeof(float)>>>(
        edge_emb, edge_y0, edge_y1, edge_index, Wr1, Wr2);
    k_out<<<(N_NODES + 127) / 128, 256, OUT_SMEM_FLOATS * sizeof(float)>>>(
        node_s, node_v, node_attrs, W2s, W2v, Wscs, Wscv, out);
}

// round 2
// speedup vs baseline: 1.0431x; 1.0431x over previous
#include <cuda_runtime.h>
#include <cstdint>

#define N_NODES 20000
#define N_EDGES 640000
#define MUL 32
#define ATTR 8
#define RB 16
#define FH 64

#define INV_M      0.17677669529663687f   // 1/sqrt(32)
#define INV_RB     0.25f                  // 1/sqrt(16)
#define INV_FH     0.125f                 // 1/sqrt(64)
#define INV_SQRT3  0.5773502691896258f
#define INV_DEG    0.17677669529663687f   // 1/sqrt(32)
#define INV_2M     0.125f                 // 1/sqrt(64)
#define INV_FAN    0.0625f                // 1/sqrt(256)
#define LOG2F_     0.6931471805599453f

// Scratch (device globals; no runtime allocation allowed)
__device__ float g_s[N_NODES * MUL];            // linear_1 scalar out   [N][32]
__device__ float g_v[N_NODES * MUL * 3];        // linear_1 vector out   [N][32][3]
__device__ float g_agg[N_NODES * MUL * 8];      // packed aggregation    [N][32][8]
// slot layout per (node,u): {s0, s1, v0x, v0y, v0z, v1x, v1y, v1z}

__device__ __forceinline__ float sspf(float x) {
    return fmaxf(x, 0.0f) + log1pf(__expf(-fabsf(x))) - LOG2F_;
}

__device__ __forceinline__ void red_add_v4(float* addr, float a, float b, float c, float d) {
    asm volatile("red.global.add.v4.f32 [%0], {%1,%2,%3,%4};"
                 :: "l"(addr), "f"(a), "f"(b), "f"(c), "f"(d) : "memory");
}

// ---- packed f32x2 helpers (FFMA2 path, PTX-only on sm_103a) ----
__device__ __forceinline__ unsigned long long pack2(float x, float y) {
    unsigned long long r;
    asm("mov.b64 %0, {%1,%2};" : "=l"(r) : "f"(x), "f"(y));
    return r;
}
__device__ __forceinline__ void unpack2(float& x, float& y, unsigned long long r) {
    asm("mov.b64 {%0,%1}, %2;" : "=f"(x), "=f"(y) : "l"(r));
}
__device__ __forceinline__ void fma2(unsigned long long& d, unsigned long long a,
                                     unsigned long long b) {
    asm("fma.rn.f32x2 %0, %1, %2, %0;" : "+l"(d) : "l"(a), "l"(b));
}
__device__ __forceinline__ unsigned long long mul2(unsigned long long a, unsigned long long b) {
    unsigned long long r;
    asm("mul.rn.f32x2 %0, %1, %2;" : "=l"(r) : "l"(a), "l"(b));
    return r;
}

// ---------------------------------------------------------------------------
// Kernel 0: zero the aggregation buffer
// ---------------------------------------------------------------------------
__global__ void k_zero() {
    int i = blockIdx.x * blockDim.x + threadIdx.x;
    float4* p = reinterpret_cast<float4*>(g_agg);
    p[i] = make_float4(0.f, 0.f, 0.f, 0.f);
}

// ---------------------------------------------------------------------------
// Kernel 1: linear_1 (unchanged — small)
// ---------------------------------------------------------------------------
__global__ void k_lin1(const float* __restrict__ node_s,
                       const float* __restrict__ node_v,
                       const float* __restrict__ W1s,
                       const float* __restrict__ W1v) {
    __shared__ float sW1s[32 * 32];
    __shared__ float sW1v[32 * 32];
    int tid = threadIdx.x;
    for (int i = tid; i < 1024; i += 256) {
        sW1s[i] = W1s[i] * INV_M;
        sW1v[i] = W1v[i] * INV_M;
    }
    __syncthreads();

    int gt = blockIdx.x * 256 + tid;
    int node = gt >> 1;
    int h = gt & 1;
    if (node >= N_NODES) return;

    float accs[16];
    float accv[16][3];
#pragma unroll
    for (int w = 0; w < 16; w++) { accs[w] = 0.f; accv[w][0] = accv[w][1] = accv[w][2] = 0.f; }

    const float* srow = node_s + node * 32;
    const float* vrow = node_v + node * 96;
    for (int u = 0; u < 32; u++) {
        float su = srow[u];
        float vx = vrow[u * 3 + 0], vy = vrow[u * 3 + 1], vz = vrow[u * 3 + 2];
        const float* ws = &sW1s[u * 32 + h * 16];
        const float* wv = &sW1v[u * 32 + h * 16];
#pragma unroll
        for (int w = 0; w < 16; w++) {
            accs[w]    += su * ws[w];
            accv[w][0] += vx * wv[w];
            accv[w][1] += vy * wv[w];
            accv[w][2] += vz * wv[w];
        }
    }
    float* so = g_s + node * 32 + h * 16;
    float* vo = g_v + node * 96 + h * 48;
#pragma unroll
    for (int w = 0; w < 16; w++) {
        so[w] = accs[w];
        vo[w * 3 + 0] = accv[w][0];
        vo[w * 3 + 1] = accv[w][1];
        vo[w * 3 + 2] = accv[w][2];
    }
}

// ---------------------------------------------------------------------------
// Kernel 2: edge kernel — radial MLP (GEMM2 in packed f32x2) + TP + scatter
// Shared (floats): Wr1[16*64] | Wr2dup[64*128*2] | emb[128*17] | h[64*128]
// ---------------------------------------------------------------------------
#define ET 128
#define EDGE_SMEM_FLOATS (1024 + 16384 + 128 * 17 + 8192)

__global__ void __launch_bounds__(256)
k_edge(const float* __restrict__ emb,
       const float* __restrict__ y0,
       const float* __restrict__ y1,
       const int*   __restrict__ eidx,
       const float* __restrict__ Wr1,
       const float* __restrict__ Wr2) {
    extern __shared__ float sm[];
    float*  sWr1  = sm;                        // [16][64] * INV_RB
    float2* sWr2d = (float2*)(sm + 1024);      // [64][128] duplicated, scaled
    float*  semb  = sm + 1024 + 16384;         // [128][17]
    float*  sh    = semb + 128 * 17;           // [64][128] (float4 per (k, te))

    int tid = threadIdx.x;
    int e0 = blockIdx.x * ET;

    for (int i = tid; i < 1024; i += 256) sWr1[i] = Wr1[i] * INV_RB;
    for (int i = tid; i < 8192; i += 256) {
        int col = i & 127;
        // fold INV_FH, INV_DEG, and path-w4's INV_SQRT3 into the weights
        float sc = INV_FH * INV_DEG * ((col >= 96) ? INV_SQRT3 : 1.0f);
        float w = Wr2[i] * sc;
        sWr2d[i] = make_float2(w, w);
    }
    for (int i = tid; i < ET * RB; i += 256) {
        int e = i >> 4, k = i & 15;
        semb[e * 17 + k] = emb[e0 * RB + i];
    }
    __syncthreads();

    int te = tid & 31;     // edge group: edges te*4 .. te*4+3
    int th = tid >> 5;     // 0..7
    int to = th;

    // ---- GEMM1: h[e][hh] = ssp( emb[e] . Wr1[:,hh] ), hh = th*8 + m ----
    float acc1[4][8];
#pragma unroll
    for (int j = 0; j < 4; j++)
#pragma unroll
        for (int m = 0; m < 8; m++) acc1[j][m] = 0.f;

    for (int k = 0; k < 16; k++) {
        float em[4];
#pragma unroll
        for (int j = 0; j < 4; j++) em[j] = semb[(te * 4 + j) * 17 + k];
        float wr[8];
#pragma unroll
        for (int m = 0; m < 8; m++) wr[m] = sWr1[k * 64 + th * 8 + m];
#pragma unroll
        for (int j = 0; j < 4; j++)
#pragma unroll
            for (int m = 0; m < 8; m++) acc1[j][m] += em[j] * wr[m];
    }
    float4* sh4 = reinterpret_cast<float4*>(sh);
#pragma unroll
    for (int m = 0; m < 8; m++) {
        float4 hv;
        hv.x = sspf(acc1[0][m]);
        hv.y = sspf(acc1[1][m]);
        hv.z = sspf(acc1[2][m]);
        hv.w = sspf(acc1[3][m]);
        sh4[(th * 8 + m) * 32 + te] = hv;
    }
    __syncthreads();

    // ---- GEMM2 (packed f32x2): w[e][o], o = to + 8*jj ----
    unsigned long long acc01[16], acc23[16];
#pragma unroll
    for (int jj = 0; jj < 16; jj++) { acc01[jj] = 0ull; acc23[jj] = 0ull; }

    const ulonglong2* sh2 = reinterpret_cast<const ulonglong2*>(sh);
    const unsigned long long* w64 = reinterpret_cast<const unsigned long long*>(sWr2d);
    for (int k = 0; k < 64; k++) {
        ulonglong2 hh = sh2[k * 32 + te];      // (h_e0,h_e1) , (h_e2,h_e3)
#pragma unroll
        for (int jj = 0; jj < 16; jj++) {
            unsigned long long wv = w64[k * 128 + to + 8 * jj];  // warp-broadcast LDS.64
            fma2(acc01[jj], hh.x, wv);
            fma2(acc23[jj], hh.y, wv);
        }
    }

    float accf[4][16];
#pragma unroll
    for (int jj = 0; jj < 16; jj++) {
        unpack2(accf[0][jj], accf[1][jj], acc01[jj]);
        unpack2(accf[2][jj], accf[3][jj], acc23[jj]);
    }

    // ---- CG tensor product + vector-atomic scatter (INV_DEG pre-folded) ----
#pragma unroll
    for (int j = 0; j < 4; j++) {
        int e = e0 + te * 4 + j;
        int src = eidx[e];
        int dst = eidx[N_EDGES + e];
        float yy0 = y0[e];
        float y1x = y1[e * 3 + 0], y1y = y1[e * 3 + 1], y1z = y1[e * 3 + 2];
        const float* sp = g_s + src * 32;
        const float* vp = g_v + src * 96;
        float* ap = g_agg + (size_t)dst * 256;
#pragma unroll
        for (int uu = 0; uu < 4; uu++) {
            int u = to + 8 * uu;
            float w1 = accf[j][0 + uu];
            float w2 = accf[j][4 + uu];
            float w3 = accf[j][8 + uu];
            float w4 = accf[j][12 + uu];
            float se = sp[u];
            float vx = vp[u * 3 + 0], vy = vp[u * 3 + 1], vz = vp[u * 3 + 2];

            float s0 = w1 * (se * yy0);
            float s1 = w4 * (vx * y1x + vy * y1y + vz * y1z);
            float a  = w2 * se;
            float v0x = a * y1x, v0y = a * y1y, v0z = a * y1z;
            float b  = w3 * yy0;
            float v1x = b * vx, v1y = b * vy, v1z = b * vz;

            float* q = ap + u * 8;
            red_add_v4(q,     s0,  s1,  v0x, v0y);
            red_add_v4(q + 4, v0z, v1x, v1y, v1z);
        }
    }
}

// ---------------------------------------------------------------------------
// Kernel 3: linear_2 + self-connection + output
// 8 threads/node (part owns 4 outputs = 2 f32x2 pairs), 32 nodes/block.
// Self-connection factored: T[u,w] = sum_v a_v W[u,v,w] shared across comps.
// ---------------------------------------------------------------------------
#define OUT_SMEM_FLOATS (2048 + 2048 + 8192 + 8192)

__global__ void __launch_bounds__(256)
k_out(const float* __restrict__ node_s,
      const float* __restrict__ node_v,
      const float* __restrict__ attrs,
      const float* __restrict__ W2s,
      const float* __restrict__ W2v,
      const float* __restrict__ Wscs,
      const float* __restrict__ Wscv,
      float* __restrict__ out) {
    extern __shared__ float sm[];
    float* sW2s  = sm;                  // [64][32] * INV_2M
    float* sW2v  = sW2s + 2048;         // [64][32] * INV_2M
    float* sWscs = sW2v + 2048;         // [32*8][32] * INV_FAN
    float* sWscv = sWscs + 8192;        // [32*8][32] * INV_FAN

    int tid = threadIdx.x;
    for (int i = tid; i < 2048; i += 256) { sW2s[i]  = W2s[i]  * INV_2M;  sW2v[i]  = W2v[i]  * INV_2M; }
    for (int i = tid; i < 8192; i += 256) { sWscs[i] = Wscs[i] * INV_FAN; sWscv[i] = Wscv[i] * INV_FAN; }
    __syncthreads();

    int node = blockIdx.x * 32 + (tid >> 3);
    int part = tid & 7;                 // owns outputs w in [part*4, part*4+4)
    int wo = part * 4;

    unsigned long long accs2[2] = {0ull, 0ull};
    unsigned long long accv2[3][2] = {{0ull, 0ull}, {0ull, 0ull}, {0ull, 0ull}};

    // ---- linear_2 on aggregated messages ----
    const float4* ag = reinterpret_cast<const float4*>(g_agg + (size_t)node * 256);
    for (int u = 0; u < 32; u++) {
        float4 A = ag[u * 2 + 0];   // {s0, s1, v0x, v0y}
        float4 B = ag[u * 2 + 1];   // {v0z, v1x, v1y, v1z}
#pragma unroll
        for (int half = 0; half < 2; half++) {
            int k = half * 32 + u;
            const unsigned long long* rs = (const unsigned long long*)&sW2s[k * 32 + wo];
            const unsigned long long* rv = (const unsigned long long*)&sW2v[k * 32 + wo];
            float as  = half ? A.y : A.x;
            float avx = half ? B.y : A.z;
            float avy = half ? B.z : A.w;
            float avz = half ? B.w : B.x;
            unsigned long long as2  = pack2(as, as);
            unsigned long long avx2 = pack2(avx, avx);
            unsigned long long avy2 = pack2(avy, avy);
            unsigned long long avz2 = pack2(avz, avz);
#pragma unroll
            for (int p = 0; p < 2; p++) {
                unsigned long long ws = rs[p];
                unsigned long long wv = rv[p];
                fma2(accs2[p], as2, ws);
                fma2(accv2[0][p], avx2, wv);
                fma2(accv2[1][p], avy2, wv);
                fma2(accv2[2][p], avz2, wv);
            }
        }
    }

    // ---- self connection (factored via T[u,w] = sum_v a_v W[u,v,w]) ----
    unsigned long long at2[8];
    const float* arow = attrs + node * 8;
#pragma unroll
    for (int v = 0; v < 8; v++) { float a = arow[v]; at2[v] = pack2(a, a); }

    const float* srow = node_s + node * 32;
    const float* vrow = node_v + node * 96;
    for (int u = 0; u < 32; u++) {
        float su = srow[u];
        float vx = vrow[u * 3 + 0], vy = vrow[u * 3 + 1], vz = vrow[u * 3 + 2];
        unsigned long long Ts[2] = {0ull, 0ull};
        unsigned long long Tv[2] = {0ull, 0ull};
#pragma unroll
        for (int v = 0; v < 8; v++) {
            const unsigned long long* ps = (const unsigned long long*)&sWscs[(u * 8 + v) * 32 + wo];
            const unsigned long long* pv = (const unsigned long long*)&sWscv[(u * 8 + v) * 32 + wo];
            fma2(Ts[0], at2[v], ps[0]);
            fma2(Ts[1], at2[v], ps[1]);
            fma2(Tv[0], at2[v], pv[0]);
            fma2(Tv[1], at2[v], pv[1]);
        }
        unsigned long long su2 = pack2(su, su);
        unsigned long long vx2 = pack2(vx, vx);
        unsigned long long vy2 = pack2(vy, vy);
        unsigned long long vz2 = pack2(vz, vz);
#pragma unroll
        for (int p = 0; p < 2; p++) {
            fma2(accs2[p], su2, Ts[p]);
            fma2(accv2[0][p], vx2, Tv[p]);
            fma2(accv2[1][p], vy2, Tv[p]);
            fma2(accv2[2][p], vz2, Tv[p]);
        }
    }

    // ---- write output: [out_s(32) | out_v(96 = w*3+i)] ----
    float* o = out + (size_t)node * 128;
#pragma unroll
    for (int p = 0; p < 2; p++) {
        float s0, s1;
        unpack2(s0, s1, accs2[p]);
        float v0[3], v1[3];
        unpack2(v0[0], v1[0], accv2[0][p]);
        unpack2(v0[1], v1[1], accv2[1][p]);
        unpack2(v0[2], v1[2], accv2[2][p]);
        int w0 = wo + p * 2;
        o[w0]     = s0;
        o[w0 + 1] = s1;
        o[32 + w0 * 3 + 0] = v0[0];
        o[32 + w0 * 3 + 1] = v0[1];
        o[32 + w0 * 3 + 2] = v0[2];
        o[32 + (w0 + 1) * 3 + 0] = v1[0];
        o[32 + (w0 + 1) * 3 + 1] = v1[1];
        o[32 + (w0 + 1) * 3 + 2] = v1[2];
    }
}

// ---------------------------------------------------------------------------
extern "C" void kernel_launch(void* const* d_in, const int* in_sizes, int n_in,
                              void* d_out, int out_size) {
    const float* node_s     = (const float*)d_in[0];
    const float* node_v     = (const float*)d_in[1];
    const float* node_attrs = (const float*)d_in[2];
    const float* edge_emb   = (const float*)d_in[3];
    const float* edge_y0    = (const float*)d_in[4];
    const float* edge_y1    = (const float*)d_in[5];
    const int*   edge_index = (const int*)d_in[6];
    const float* W1s        = (const float*)d_in[7];
    const float* W1v        = (const float*)d_in[8];
    const float* Wr1        = (const float*)d_in[9];
    const float* Wr2        = (const float*)d_in[10];
    const float* W2s        = (const float*)d_in[11];
    const float* W2v        = (const float*)d_in[12];
    const float* Wscs       = (const float*)d_in[13];
    const float* Wscv       = (const float*)d_in[14];
    float* out = (float*)d_out;

    cudaFuncSetAttribute(k_edge, cudaFuncAttributeMaxDynamicSharedMemorySize,
                         EDGE_SMEM_FLOATS * sizeof(float));
    cudaFuncSetAttribute(k_out, cudaFuncAttributeMaxDynamicSharedMemorySize,
                         OUT_SMEM_FLOATS * sizeof(float));

    k_zero<<<5000, 256>>>();
    k_lin1<<<(2 * N_NODES + 255) / 256, 256>>>(node_s, node_v, W1s, W1v);
    k_edge<<<N_EDGES / ET, 256, EDGE_SMEM_FLOATS * sizeof(float)>>>(
        edge_emb, edge_y0, edge_y1, edge_index, Wr1, Wr2);
    k_out<<<(N_NODES * 8) / 256, 256, OUT_SMEM_FLOATS * sizeof(float)>>>(
        node_s, node_v, node_attrs, W2s, W2v, Wscs, Wscv, out);
}

// round 3
// speedup vs baseline: 1.1020x; 1.0564x over previous
#include <cuda_runtime.h>
#include <cstdint>

#define N_NODES 20000
#define N_EDGES 640000
#define MUL 32
#define ATTR 8
#define RB 16
#define FH 64

#define INV_M      0.17677669529663687f
#define INV_RB     0.25f
#define INV_FH     0.125f
#define INV_SQRT3  0.5773502691896258f
#define INV_DEG    0.17677669529663687f
#define INV_2M     0.125f
#define INV_FAN    0.0625f
#define LOG2F_     0.6931471805599453f

// Scratch (device globals)
__device__ float g_s[N_NODES * MUL];
__device__ float g_v[N_NODES * MUL * 3];
__device__ float g_agg[N_NODES * MUL * 8];
// sort scratch
__device__ int g_cnt[N_NODES];
__device__ int g_pos[N_NODES];
__device__ int g_off[N_NODES + 1];
__device__ int g_perm[N_EDGES];

__device__ __forceinline__ float sspf(float x) {
    return fmaxf(x, 0.0f) + log1pf(__expf(-fabsf(x))) - LOG2F_;
}

__device__ __forceinline__ void red_add_v4(float* addr, float a, float b, float c, float d) {
    asm volatile("red.global.add.v4.f32 [%0], {%1,%2,%3,%4};"
                 :: "l"(addr), "f"(a), "f"(b), "f"(c), "f"(d) : "memory");
}

// ---- packed f32x2 helpers ----
__device__ __forceinline__ unsigned long long pack2(float x, float y) {
    unsigned long long r;
    asm("mov.b64 %0, {%1,%2};" : "=l"(r) : "f"(x), "f"(y));
    return r;
}
__device__ __forceinline__ void unpack2(float& x, float& y, unsigned long long r) {
    asm("mov.b64 {%0,%1}, %2;" : "=f"(x), "=f"(y) : "l"(r));
}
__device__ __forceinline__ void fma2(unsigned long long& d, unsigned long long a,
                                     unsigned long long b) {
    asm("fma.rn.f32x2 %0, %1, %2, %0;" : "+l"(d) : "l"(a), "l"(b));
}

// ---------------------------------------------------------------------------
// Kernel 0: zero agg + counters
// ---------------------------------------------------------------------------
__global__ void k_zero() {
    int i = blockIdx.x * blockDim.x + threadIdx.x;
    float4* p = reinterpret_cast<float4*>(g_agg);
    p[i] = make_float4(0.f, 0.f, 0.f, 0.f);
    if (i < N_NODES) { g_cnt[i] = 0; g_pos[i] = 0; }
}

// ---------------------------------------------------------------------------
// Sort kernels: histogram -> scan -> rank scatter
// ---------------------------------------------------------------------------
__global__ void k_hist(const int* __restrict__ eidx) {
    int e = blockIdx.x * blockDim.x + threadIdx.x;
    if (e < N_EDGES) atomicAdd(&g_cnt[eidx[N_EDGES + e]], 1);
}

__global__ void k_scan() {   // single block, 1024 threads, 20 elems/thread
    __shared__ int sh[1024];
    int tid = threadIdx.x;
    int base = tid * 20;
    int loc[20];
    int s = 0;
#pragma unroll
    for (int j = 0; j < 20; j++) {
        int idx = base + j;
        int c = (idx < N_NODES) ? g_cnt[idx] : 0;
        loc[j] = s;
        s += c;
    }
    sh[tid] = s;
    __syncthreads();
    for (int off = 1; off < 1024; off <<= 1) {
        int v = (tid >= off) ? sh[tid - off] : 0;
        __syncthreads();
        sh[tid] += v;
        __syncthreads();
    }
    int pre = (tid == 0) ? 0 : sh[tid - 1];
#pragma unroll
    for (int j = 0; j < 20; j++) {
        int idx = base + j;
        if (idx < N_NODES) g_off[idx] = pre + loc[j];
    }
    if (tid == 1023) g_off[N_NODES] = sh[1023];
}

__global__ void k_scatter(const int* __restrict__ eidx) {
    int e = blockIdx.x * blockDim.x + threadIdx.x;
    if (e < N_EDGES) {
        int dst = eidx[N_EDGES + e];
        int r = atomicAdd(&g_pos[dst], 1);
        g_perm[g_off[dst] + r] = e;
    }
}

// ---------------------------------------------------------------------------
// Kernel 1: linear_1
// ---------------------------------------------------------------------------
__global__ void k_lin1(const float* __restrict__ node_s,
                       const float* __restrict__ node_v,
                       const float* __restrict__ W1s,
                       const float* __restrict__ W1v) {
    __shared__ float sW1s[1024];
    __shared__ float sW1v[1024];
    int tid = threadIdx.x;
    for (int i = tid; i < 1024; i += 256) {
        sW1s[i] = W1s[i] * INV_M;
        sW1v[i] = W1v[i] * INV_M;
    }
    __syncthreads();

    int gt = blockIdx.x * 256 + tid;
    int node = gt >> 1;
    int h = gt & 1;
    if (node >= N_NODES) return;

    float accs[16];
    float accv[16][3];
#pragma unroll
    for (int w = 0; w < 16; w++) { accs[w] = 0.f; accv[w][0] = accv[w][1] = accv[w][2] = 0.f; }

    const float* srow = node_s + node * 32;
    const float* vrow = node_v + node * 96;
    for (int u = 0; u < 32; u++) {
        float su = srow[u];
        float vx = vrow[u * 3 + 0], vy = vrow[u * 3 + 1], vz = vrow[u * 3 + 2];
        const float* ws = &sW1s[u * 32 + h * 16];
        const float* wv = &sW1v[u * 32 + h * 16];
#pragma unroll
        for (int w = 0; w < 16; w++) {
            accs[w]    += su * ws[w];
            accv[w][0] += vx * wv[w];
            accv[w][1] += vy * wv[w];
            accv[w][2] += vz * wv[w];
        }
    }
    float* so = g_s + node * 32 + h * 16;
    float* vo = g_v + node * 96 + h * 48;
#pragma unroll
    for (int w = 0; w < 16; w++) {
        so[w] = accs[w];
        vo[w * 3 + 0] = accv[w][0];
        vo[w * 3 + 1] = accv[w][1];
        vo[w * 3 + 2] = accv[w][2];
    }
}

// ---------------------------------------------------------------------------
// Kernel 2: edge kernel on dst-SORTED edges.
// Radial MLP + TP + register-run-accumulated scatter.
// Shared (floats): Wr1[1024] | Wr2[8192] | emb[128*17] | h[8192] | meta
// ---------------------------------------------------------------------------
#define ET 128
#define EDGE_SMEM_FLOATS (1024 + 8192 + 128 * 17 + 8192 + 128 * 3 + 128 + 384)

__global__ void __launch_bounds__(256)
k_edge(const float* __restrict__ emb,
       const float* __restrict__ y0,
       const float* __restrict__ y1,
       const int*   __restrict__ eidx,
       const float* __restrict__ Wr1,
       const float* __restrict__ Wr2) {
    extern __shared__ float sm[];
    float* sWr1 = sm;                          // [16][64] * INV_RB
    float* sWr2 = sWr1 + 1024;                 // [64][128] scaled
    float* semb = sWr2 + 8192;                 // [128][17]
    float* sh   = semb + 128 * 17;             // [64][128] (float4 over edge quads)
    int*   sperm = (int*)(sh + 8192);          // [128]
    int*   ssrc  = sperm + 128;                // [128]
    int*   sdst  = ssrc + 128;                 // [128]
    float* sy0   = (float*)(sdst + 128);       // [128]
    float* sy1   = sy0 + 128;                  // [128*3]

    int tid = threadIdx.x;
    int p0 = blockIdx.x * ET;

    if (tid < 128) sperm[tid] = g_perm[p0 + tid];
    for (int i = tid; i < 1024; i += 256) sWr1[i] = Wr1[i] * INV_RB;
    for (int i = tid; i < 8192; i += 256) {
        int col = i & 127;
        float sc = INV_FH * INV_DEG * ((col >= 96) ? INV_SQRT3 : 1.0f);
        sWr2[i] = Wr2[i] * sc;
    }
    __syncthreads();

    if (tid < 128) {
        int e = sperm[tid];
        ssrc[tid] = eidx[e];
        sdst[tid] = eidx[N_EDGES + e];
        sy0[tid] = y0[e];
    }
    for (int i = tid; i < 384; i += 256) {
        int pos = i / 3, comp = i - pos * 3;
        sy1[i] = y1[sperm[pos] * 3 + comp];
    }
    for (int i = tid; i < ET * RB; i += 256) {
        int pos = i >> 4, k = i & 15;
        semb[pos * 17 + k] = emb[sperm[pos] * 16 + k];
    }
    __syncthreads();

    int te = tid & 31;     // edge window: positions te*4 .. te*4+3 (sorted!)
    int th = tid >> 5;     // 0..7
    int to = th;

    // ---- GEMM1 ----
    float acc1[4][8];
#pragma unroll
    for (int j = 0; j < 4; j++)
#pragma unroll
        for (int m = 0; m < 8; m++) acc1[j][m] = 0.f;

    for (int k = 0; k < 16; k++) {
        float em[4];
#pragma unroll
        for (int j = 0; j < 4; j++) em[j] = semb[(te * 4 + j) * 17 + k];
        float wr[8];
#pragma unroll
        for (int m = 0; m < 8; m++) wr[m] = sWr1[k * 64 + th * 8 + m];
#pragma unroll
        for (int j = 0; j < 4; j++)
#pragma unroll
            for (int m = 0; m < 8; m++) acc1[j][m] += em[j] * wr[m];
    }
    float4* sh4 = reinterpret_cast<float4*>(sh);
#pragma unroll
    for (int m = 0; m < 8; m++) {
        float4 hv;
        hv.x = sspf(acc1[0][m]);
        hv.y = sspf(acc1[1][m]);
        hv.z = sspf(acc1[2][m]);
        hv.w = sspf(acc1[3][m]);
        sh4[(th * 8 + m) * 32 + te] = hv;
    }
    __syncthreads();

    // ---- GEMM2 (f32x2 over edge pairs) ----
    unsigned long long acc01[16], acc23[16];
#pragma unroll
    for (int jj = 0; jj < 16; jj++) { acc01[jj] = 0ull; acc23[jj] = 0ull; }

    const ulonglong2* sh2 = reinterpret_cast<const ulonglong2*>(sh);
    for (int k = 0; k < 64; k++) {
        ulonglong2 hh = sh2[k * 32 + te];
#pragma unroll
        for (int jj = 0; jj < 16; jj++) {
            float w = sWr2[k * 128 + to + 8 * jj];   // warp-broadcast
            unsigned long long w2p = pack2(w, w);
            fma2(acc01[jj], hh.x, w2p);
            fma2(acc23[jj], hh.y, w2p);
        }
    }

    float accf[4][16];
#pragma unroll
    for (int jj = 0; jj < 16; jj++) {
        unpack2(accf[0][jj], accf[1][jj], acc01[jj]);
        unpack2(accf[2][jj], accf[3][jj], acc23[jj]);
    }

    // ---- TP + register-run accumulation over sorted dst ----
    float A[4][8];
#pragma unroll
    for (int uu = 0; uu < 4; uu++)
#pragma unroll
        for (int q = 0; q < 8; q++) A[uu][q] = 0.f;

    int cur = sdst[te * 4];
#pragma unroll
    for (int j = 0; j < 4; j++) {
        int pos = te * 4 + j;
        int d = sdst[pos];
        if (d != cur) {
            // flush
#pragma unroll
            for (int uu = 0; uu < 4; uu++) {
                float* q = g_agg + (size_t)cur * 256 + (to + 8 * uu) * 8;
                red_add_v4(q,     A[uu][0], A[uu][1], A[uu][2], A[uu][3]);
                red_add_v4(q + 4, A[uu][4], A[uu][5], A[uu][6], A[uu][7]);
#pragma unroll
                for (int qq = 0; qq < 8; qq++) A[uu][qq] = 0.f;
            }
            cur = d;
        }
        int src = ssrc[pos];
        float yy0 = sy0[pos];
        float y1x = sy1[pos * 3 + 0], y1y = sy1[pos * 3 + 1], y1z = sy1[pos * 3 + 2];
        const float* sp = g_s + src * 32;
        const float* vp = g_v + src * 96;
#pragma unroll
        for (int uu = 0; uu < 4; uu++) {
            int u = to + 8 * uu;
            float w1 = accf[j][0 + uu];
            float w2 = accf[j][4 + uu];
            float w3 = accf[j][8 + uu];
            float w4 = accf[j][12 + uu];
            float se = sp[u];
            float vx = vp[u * 3 + 0], vy = vp[u * 3 + 1], vz = vp[u * 3 + 2];

            A[uu][0] += w1 * (se * yy0);
            A[uu][1] += w4 * (vx * y1x + vy * y1y + vz * y1z);
            float a = w2 * se;
            A[uu][2] += a * y1x;
            A[uu][3] += a * y1y;
            A[uu][4] += a * y1z;
            float b = w3 * yy0;
            A[uu][5] += b * vx;
            A[uu][6] += b * vy;
            A[uu][7] += b * vz;
        }
    }
    // final flush
#pragma unroll
    for (int uu = 0; uu < 4; uu++) {
        float* q = g_agg + (size_t)cur * 256 + (to + 8 * uu) * 8;
        red_add_v4(q,     A[uu][0], A[uu][1], A[uu][2], A[uu][3]);
        red_add_v4(q + 4, A[uu][4], A[uu][5], A[uu][6], A[uu][7]);
    }
}

// ---------------------------------------------------------------------------
// Kernel 3: linear_2 + self-connection (LDS.128 weight loads)
// ---------------------------------------------------------------------------
#define OUT_SMEM_FLOATS (2048 + 2048 + 8192 + 8192)

__global__ void __launch_bounds__(256)
k_out(const float* __restrict__ node_s,
      const float* __restrict__ node_v,
      const float* __restrict__ attrs,
      const float* __restrict__ W2s,
      const float* __restrict__ W2v,
      const float* __restrict__ Wscs,
      const float* __restrict__ Wscv,
      float* __restrict__ out) {
    extern __shared__ float sm[];
    float* sW2s  = sm;
    float* sW2v  = sW2s + 2048;
    float* sWscs = sW2v + 2048;
    float* sWscv = sWscs + 8192;

    int tid = threadIdx.x;
    for (int i = tid; i < 2048; i += 256) { sW2s[i]  = W2s[i]  * INV_2M;  sW2v[i]  = W2v[i]  * INV_2M; }
    for (int i = tid; i < 8192; i += 256) { sWscs[i] = Wscs[i] * INV_FAN; sWscv[i] = Wscv[i] * INV_FAN; }
    __syncthreads();

    int node = blockIdx.x * 32 + (tid >> 3);
    int part = tid & 7;
    int wo = part * 4;

    unsigned long long accs2[2] = {0ull, 0ull};
    unsigned long long accv2[3][2] = {{0ull, 0ull}, {0ull, 0ull}, {0ull, 0ull}};

    // ---- linear_2 ----
    const float4* ag = reinterpret_cast<const float4*>(g_agg + (size_t)node * 256);
#pragma unroll 4
    for (int u = 0; u < 32; u++) {
        float4 Aq = ag[u * 2 + 0];
        float4 Bq = ag[u * 2 + 1];
#pragma unroll
        for (int half = 0; half < 2; half++) {
            int k = half * 32 + u;
            ulonglong2 ws = *(const ulonglong2*)&sW2s[k * 32 + wo];
            ulonglong2 wv = *(const ulonglong2*)&sW2v[k * 32 + wo];
            float as  = half ? Aq.y : Aq.x;
            float avx = half ? Bq.y : Aq.z;
            float avy = half ? Bq.z : Aq.w;
            float avz = half ? Bq.w : Bq.x;
            unsigned long long as2  = pack2(as, as);
            unsigned long long avx2 = pack2(avx, avx);
            unsigned long long avy2 = pack2(avy, avy);
            unsigned long long avz2 = pack2(avz, avz);
            fma2(accs2[0], as2, ws.x);
            fma2(accs2[1], as2, ws.y);
            fma2(accv2[0][0], avx2, wv.x);
            fma2(accv2[0][1], avx2, wv.y);
            fma2(accv2[1][0], avy2, wv.x);
            fma2(accv2[1][1], avy2, wv.y);
            fma2(accv2[2][0], avz2, wv.x);
            fma2(accv2[2][1], avz2, wv.y);
        }
    }

    // ---- self connection, factored T[u,w] = sum_v a_v W[u,v,w] ----
    unsigned long long at2[8];
    const float* arow = attrs + node * 8;
#pragma unroll
    for (int v = 0; v < 8; v++) { float a = arow[v]; at2[v] = pack2(a, a); }

    const float* srow = node_s + node * 32;
    const float* vrow = node_v + node * 96;
#pragma unroll 2
    for (int u = 0; u < 32; u++) {
        float su = srow[u];
        float vx = vrow[u * 3 + 0], vy = vrow[u * 3 + 1], vz = vrow[u * 3 + 2];
        unsigned long long Ts[2] = {0ull, 0ull};
        unsigned long long Tv[2] = {0ull, 0ull};
#pragma unroll
        for (int v = 0; v < 8; v++) {
            ulonglong2 ps = *(const ulonglong2*)&sWscs[(u * 8 + v) * 32 + wo];
            ulonglong2 pv = *(const ulonglong2*)&sWscv[(u * 8 + v) * 32 + wo];
            fma2(Ts[0], at2[v], ps.x);
            fma2(Ts[1], at2[v], ps.y);
            fma2(Tv[0], at2[v], pv.x);
            fma2(Tv[1], at2[v], pv.y);
        }
        unsigned long long su2 = pack2(su, su);
        unsigned long long vx2 = pack2(vx, vx);
        unsigned long long vy2 = pack2(vy, vy);
        unsigned long long vz2 = pack2(vz, vz);
#pragma unroll
        for (int p = 0; p < 2; p++) {
            fma2(accs2[p], su2, Ts[p]);
            fma2(accv2[0][p], vx2, Tv[p]);
            fma2(accv2[1][p], vy2, Tv[p]);
            fma2(accv2[2][p], vz2, Tv[p]);
        }
    }

    // ---- output ----
    float* o = out + (size_t)node * 128;
#pragma unroll
    for (int p = 0; p < 2; p++) {
        float s0, s1;
        unpack2(s0, s1, accs2[p]);
        float v0[3], v1[3];
        unpack2(v0[0], v1[0], accv2[0][p]);
        unpack2(v0[1], v1[1], accv2[1][p]);
        unpack2(v0[2], v1[2], accv2[2][p]);
        int w0 = wo + p * 2;
        o[w0]     = s0;
        o[w0 + 1] = s1;
        o[32 + w0 * 3 + 0] = v0[0];
        o[32 + w0 * 3 + 1] = v0[1];
        o[32 + w0 * 3 + 2] = v0[2];
        o[32 + (w0 + 1) * 3 + 0] = v1[0];
        o[32 + (w0 + 1) * 3 + 1] = v1[1];
        o[32 + (w0 + 1) * 3 + 2] = v1[2];
    }
}

// ---------------------------------------------------------------------------
extern "C" void kernel_launch(void* const* d_in, const int* in_sizes, int n_in,
                              void* d_out, int out_size) {
    const float* node_s     = (const float*)d_in[0];
    const float* node_v     = (const float*)d_in[1];
    const float* node_attrs = (const float*)d_in[2];
    const float* edge_emb   = (const float*)d_in[3];
    const float* edge_y0    = (const float*)d_in[4];
    const float* edge_y1    = (const float*)d_in[5];
    const int*   edge_index = (const int*)d_in[6];
    const float* W1s        = (const float*)d_in[7];
    const float* W1v        = (const float*)d_in[8];
    const float* Wr1        = (const float*)d_in[9];
    const float* Wr2        = (const float*)d_in[10];
    const float* W2s        = (const float*)d_in[11];
    const float* W2v        = (const float*)d_in[12];
    const float* Wscs       = (const float*)d_in[13];
    const float* Wscv       = (const float*)d_in[14];
    float* out = (float*)d_out;

    cudaFuncSetAttribute(k_edge, cudaFuncAttributeMaxDynamicSharedMemorySize,
                         EDGE_SMEM_FLOATS * sizeof(float));
    cudaFuncSetAttribute(k_out, cudaFuncAttributeMaxDynamicSharedMemorySize,
                         OUT_SMEM_FLOATS * sizeof(float));

    k_zero<<<5000, 256>>>();
    k_hist<<<2500, 256>>>(edge_index);
    k_scan<<<1, 1024>>>();
    k_scatter<<<2500, 256>>>(edge_index);
    k_lin1<<<(2 * N_NODES + 255) / 256, 256>>>(node_s, node_v, W1s, W1v);
    k_edge<<<N_EDGES / ET, 256, EDGE_SMEM_FLOATS * sizeof(float)>>>(
        edge_emb, edge_y0, edge_y1, edge_index, Wr1, Wr2);
    k_out<<<(N_NODES * 8) / 256, 256, OUT_SMEM_FLOATS * sizeof(float)>>>(
        node_s, node_v, node_attrs, W2s, W2v, Wscs, Wscv, out);
}

// round 4
// speedup vs baseline: 1.5283x; 1.3868x over previous
#include <cuda_runtime.h>
#include <cstdint>

#define N_NODES 20000
#define N_EDGES 640000
#define MUL 32
#define ATTR 8
#define RB 16
#define FH 64

#define INV_M      0.17677669529663687f
#define INV_RB     0.25f
#define INV_FH     0.125f
#define INV_SQRT3  0.5773502691896258f
#define INV_DEG    0.17677669529663687f
#define INV_2M     0.125f
#define INV_FAN    0.0625f
#define LOG2F_     0.6931471805599453f

// Scratch (device globals)
__device__ float g_s[N_NODES * MUL];
__device__ float g_v[N_NODES * MUL * 3];
__device__ float g_agg[N_NODES * MUL * 8];
// sort scratch
__device__ int g_cnt[N_NODES];
__device__ int g_pos[N_NODES];
__device__ int g_off[N_NODES + 1];
__device__ int g_perm[N_EDGES];

__device__ __forceinline__ float sspf(float x) {
    return fmaxf(x, 0.0f) + log1pf(__expf(-fabsf(x))) - LOG2F_;
}

__device__ __forceinline__ void red_add_v4(float* addr, float a, float b, float c, float d) {
    asm volatile("red.global.add.v4.f32 [%0], {%1,%2,%3,%4};"
                 :: "l"(addr), "f"(a), "f"(b), "f"(c), "f"(d) : "memory");
}

// ---- packed f32x2 helpers ----
__device__ __forceinline__ unsigned long long pack2(float x, float y) {
    unsigned long long r;
    asm("mov.b64 %0, {%1,%2};" : "=l"(r) : "f"(x), "f"(y));
    return r;
}
__device__ __forceinline__ void unpack2(float& x, float& y, unsigned long long r) {
    asm("mov.b64 {%0,%1}, %2;" : "=f"(x), "=f"(y) : "l"(r));
}
__device__ __forceinline__ void fma2(unsigned long long& d, unsigned long long a,
                                     unsigned long long b) {
    asm("fma.rn.f32x2 %0, %1, %2, %0;" : "+l"(d) : "l"(a), "l"(b));
}

// ---------------------------------------------------------------------------
__global__ void k_zero() {
    int i = blockIdx.x * blockDim.x + threadIdx.x;
    float4* p = reinterpret_cast<float4*>(g_agg);
    p[i] = make_float4(0.f, 0.f, 0.f, 0.f);
    if (i < N_NODES) { g_cnt[i] = 0; g_pos[i] = 0; }
}

__global__ void k_hist(const int* __restrict__ eidx) {
    int e = blockIdx.x * blockDim.x + threadIdx.x;
    if (e < N_EDGES) atomicAdd(&g_cnt[eidx[N_EDGES + e]], 1);
}

__global__ void k_scan() {   // single block, 1024 threads, 20 elems/thread
    __shared__ int sh[1024];
    int tid = threadIdx.x;
    int base = tid * 20;
    int loc[20];
    int s = 0;
#pragma unroll
    for (int j = 0; j < 20; j++) {
        int idx = base + j;
        int c = (idx < N_NODES) ? g_cnt[idx] : 0;
        loc[j] = s;
        s += c;
    }
    sh[tid] = s;
    __syncthreads();
    for (int off = 1; off < 1024; off <<= 1) {
        int v = (tid >= off) ? sh[tid - off] : 0;
        __syncthreads();
        sh[tid] += v;
        __syncthreads();
    }
    int pre = (tid == 0) ? 0 : sh[tid - 1];
#pragma unroll
    for (int j = 0; j < 20; j++) {
        int idx = base + j;
        if (idx < N_NODES) g_off[idx] = pre + loc[j];
    }
    if (tid == 1023) g_off[N_NODES] = sh[1023];
}

__global__ void k_scatter(const int* __restrict__ eidx) {
    int e = blockIdx.x * blockDim.x + threadIdx.x;
    if (e < N_EDGES) {
        int dst = eidx[N_EDGES + e];
        int r = atomicAdd(&g_pos[dst], 1);
        g_perm[g_off[dst] + r] = e;
    }
}

// ---------------------------------------------------------------------------
// Kernel 1: linear_1
// ---------------------------------------------------------------------------
__global__ void k_lin1(const float* __restrict__ node_s,
                       const float* __restrict__ node_v,
                       const float* __restrict__ W1s,
                       const float* __restrict__ W1v) {
    __shared__ float sW1s[1024];
    __shared__ float sW1v[1024];
    int tid = threadIdx.x;
    for (int i = tid; i < 1024; i += 256) {
        sW1s[i] = W1s[i] * INV_M;
        sW1v[i] = W1v[i] * INV_M;
    }
    __syncthreads();

    int gt = blockIdx.x * 256 + tid;
    int node = gt >> 1;
    int h = gt & 1;
    if (node >= N_NODES) return;

    float accs[16];
    float accv[16][3];
#pragma unroll
    for (int w = 0; w < 16; w++) { accs[w] = 0.f; accv[w][0] = accv[w][1] = accv[w][2] = 0.f; }

    const float* srow = node_s + node * 32;
    const float* vrow = node_v + node * 96;
    for (int u = 0; u < 32; u++) {
        float su = srow[u];
        float vx = vrow[u * 3 + 0], vy = vrow[u * 3 + 1], vz = vrow[u * 3 + 2];
        const float* ws = &sW1s[u * 32 + h * 16];
        const float* wv = &sW1v[u * 32 + h * 16];
#pragma unroll
        for (int w = 0; w < 16; w++) {
            accs[w]    += su * ws[w];
            accv[w][0] += vx * wv[w];
            accv[w][1] += vy * wv[w];
            accv[w][2] += vz * wv[w];
        }
    }
    float* so = g_s + node * 32 + h * 16;
    float* vo = g_v + node * 96 + h * 48;
#pragma unroll
    for (int w = 0; w < 16; w++) {
        so[w] = accs[w];
        vo[w * 3 + 0] = accv[w][0];
        vo[w * 3 + 1] = accv[w][1];
        vo[w * 3 + 2] = accv[w][2];
    }
}

// ---------------------------------------------------------------------------
// Kernel 2: edge kernel on dst-SORTED edges.
// Radial MLP -> smem weight exchange -> warp-cooperative TP (lane = u),
// coalesced gathers, register run-accumulation, warp-coalesced red.v4 flush.
//
// Shared layout (floats):
//   phase 1/2: [0:1024) Wr1 | [1024:9216) Wr2 | [9216:11392) emb | [11392:19584) h
//   phase 3 overlay: [0:16512) sw[128][129]
//   persistent meta at [19584:): sperm(128i) ssrc(128i) sdst(128i) sy0(128) sy1(384)
// ---------------------------------------------------------------------------
#define ET 128
#define SW_PAD 129
#define EDGE_SMEM_FLOATS (19584 + 128 + 128 + 128 + 128 + 384)

__global__ void __launch_bounds__(256, 2)
k_edge(const float* __restrict__ emb,
       const float* __restrict__ y0,
       const float* __restrict__ y1,
       const int*   __restrict__ eidx,
       const float* __restrict__ Wr1,
       const float* __restrict__ Wr2) {
    extern __shared__ float sm[];
    float* sWr1 = sm;                          // [16][64] * INV_RB
    float* sWr2 = sWr1 + 1024;                 // [64][128] scaled
    float* semb = sWr2 + 8192;                 // [128][17]
    float* sh   = semb + 128 * 17;             // [64][128] (float4 over edge quads)
    float* sw   = sm;                          // overlay [128][129] after GEMM2
    int*   sperm = (int*)(sm + 19584);         // [128]
    int*   ssrc  = sperm + 128;                // [128]
    int*   sdst  = ssrc + 128;                 // [128]
    float* sy0   = (float*)(sdst + 128);       // [128]
    float* sy1   = sy0 + 128;                  // [128*3]

    int tid = threadIdx.x;
    int p0 = blockIdx.x * ET;

    if (tid < 128) sperm[tid] = g_perm[p0 + tid];
    for (int i = tid; i < 1024; i += 256) sWr1[i] = Wr1[i] * INV_RB;
    for (int i = tid; i < 8192; i += 256) {
        int col = i & 127;
        float sc = INV_FH * INV_DEG * ((col >= 96) ? INV_SQRT3 : 1.0f);
        sWr2[i] = Wr2[i] * sc;
    }
    __syncthreads();

    if (tid < 128) {
        int e = sperm[tid];
        ssrc[tid] = eidx[e];
        sdst[tid] = eidx[N_EDGES + e];
        sy0[tid] = y0[e];
    }
    for (int i = tid; i < 384; i += 256) {
        int pos = i / 3, comp = i - pos * 3;
        sy1[i] = y1[sperm[pos] * 3 + comp];
    }
    for (int i = tid; i < ET * RB; i += 256) {
        int pos = i >> 4, k = i & 15;
        semb[pos * 17 + k] = emb[sperm[pos] * 16 + k];
    }
    __syncthreads();

    int te = tid & 31;     // lane
    int th = tid >> 5;     // warp id 0..7

    // ---- GEMM1: edges te*4..te*4+3, hidden cols th*8..th*8+7 ----
    float acc1[4][8];
#pragma unroll
    for (int j = 0; j < 4; j++)
#pragma unroll
        for (int m = 0; m < 8; m++) acc1[j][m] = 0.f;

    for (int k = 0; k < 16; k++) {
        float em[4];
#pragma unroll
        for (int j = 0; j < 4; j++) em[j] = semb[(te * 4 + j) * 17 + k];
        float wr[8];
#pragma unroll
        for (int m = 0; m < 8; m++) wr[m] = sWr1[k * 64 + th * 8 + m];
#pragma unroll
        for (int j = 0; j < 4; j++)
#pragma unroll
            for (int m = 0; m < 8; m++) acc1[j][m] += em[j] * wr[m];
    }
    float4* sh4 = reinterpret_cast<float4*>(sh);
#pragma unroll
    for (int m = 0; m < 8; m++) {
        float4 hv;
        hv.x = sspf(acc1[0][m]);
        hv.y = sspf(acc1[1][m]);
        hv.z = sspf(acc1[2][m]);
        hv.w = sspf(acc1[3][m]);
        sh4[(th * 8 + m) * 32 + te] = hv;
    }
    __syncthreads();

    // ---- GEMM2 (f32x2 over edge pairs): cols th + 8*jj ----
    unsigned long long acc01[16], acc23[16];
#pragma unroll
    for (int jj = 0; jj < 16; jj++) { acc01[jj] = 0ull; acc23[jj] = 0ull; }

    const ulonglong2* sh2 = reinterpret_cast<const ulonglong2*>(sh);
    for (int k = 0; k < 64; k++) {
        ulonglong2 hh = sh2[k * 32 + te];
#pragma unroll
        for (int jj = 0; jj < 16; jj++) {
            float w = sWr2[k * 128 + th + 8 * jj];   // warp-broadcast
            unsigned long long w2p = pack2(w, w);
            fma2(acc01[jj], hh.x, w2p);
            fma2(acc23[jj], hh.y, w2p);
        }
    }

    float accf[4][16];
#pragma unroll
    for (int jj = 0; jj < 16; jj++) {
        unpack2(accf[0][jj], accf[1][jj], acc01[jj]);
        unpack2(accf[2][jj], accf[3][jj], acc23[jj]);
    }
    __syncthreads();   // everyone done reading sWr2/sh

    // ---- weight exchange: sw[pos][col], col = th + 8*jj ----
#pragma unroll
    for (int j = 0; j < 4; j++) {
        int pos = te * 4 + j;
#pragma unroll
        for (int jj = 0; jj < 16; jj++) {
            sw[pos * SW_PAD + th + 8 * jj] = accf[j][jj];
        }
    }
    __syncthreads();

    // ---- warp-cooperative TP: warp th owns edges [th*16, th*16+16), lane = u ----
    int lane = te;
    float A[8];
#pragma unroll
    for (int q = 0; q < 8; q++) A[q] = 0.f;

    int base = th * 16;
    int cur = sdst[base];
#pragma unroll 4
    for (int j = 0; j < 16; j++) {
        int pos = base + j;
        int d = sdst[pos];
        if (d != cur) {   // warp-uniform
            float* q = g_agg + (size_t)cur * 256 + lane * 8;
            red_add_v4(q,     A[0], A[1], A[2], A[3]);
            red_add_v4(q + 4, A[4], A[5], A[6], A[7]);
#pragma unroll
            for (int qq = 0; qq < 8; qq++) A[qq] = 0.f;
            cur = d;
        }
        int src = ssrc[pos];
        float yy0 = sy0[pos];
        float y1x = sy1[pos * 3 + 0], y1y = sy1[pos * 3 + 1], y1z = sy1[pos * 3 + 2];
        float se = g_s[src * 32 + lane];                    // coalesced 128B
        const float* vp = g_v + src * 96 + lane * 3;        // coalesced 384B
        float vx = vp[0], vy = vp[1], vz = vp[2];
        const float* wrow = sw + pos * SW_PAD + lane;       // conflict-free LDS
        float w1 = wrow[0], w2 = wrow[32], w3 = wrow[64], w4 = wrow[96];

        A[0] += w1 * (se * yy0);
        A[1] += w4 * (vx * y1x + vy * y1y + vz * y1z);
        float a = w2 * se;
        A[2] += a * y1x; A[3] += a * y1y; A[4] += a * y1z;
        float b = w3 * yy0;
        A[5] += b * vx;  A[6] += b * vy;  A[7] += b * vz;
    }
    // final flush
    float* q = g_agg + (size_t)cur * 256 + lane * 8;
    red_add_v4(q,     A[0], A[1], A[2], A[3]);
    red_add_v4(q + 4, A[4], A[5], A[6], A[7]);
}

// ---------------------------------------------------------------------------
// Kernel 3: linear_2 + self-connection
// ---------------------------------------------------------------------------
#define OUT_SMEM_FLOATS (2048 + 2048 + 8192 + 8192)

__global__ void __launch_bounds__(256)
k_out(const float* __restrict__ node_s,
      const float* __restrict__ node_v,
      const float* __restrict__ attrs,
      const float* __restrict__ W2s,
      const float* __restrict__ W2v,
      const float* __restrict__ Wscs,
      const float* __restrict__ Wscv,
      float* __restrict__ out) {
    extern __shared__ float sm[];
    float* sW2s  = sm;
    float* sW2v  = sW2s + 2048;
    float* sWscs = sW2v + 2048;
    float* sWscv = sWscs + 8192;

    int tid = threadIdx.x;
    for (int i = tid; i < 2048; i += 256) { sW2s[i]  = W2s[i]  * INV_2M;  sW2v[i]  = W2v[i]  * INV_2M; }
    for (int i = tid; i < 8192; i += 256) { sWscs[i] = Wscs[i] * INV_FAN; sWscv[i] = Wscv[i] * INV_FAN; }
    __syncthreads();

    int node = blockIdx.x * 32 + (tid >> 3);
    int part = tid & 7;
    int wo = part * 4;

    unsigned long long accs2[2] = {0ull, 0ull};
    unsigned long long accv2[3][2] = {{0ull, 0ull}, {0ull, 0ull}, {0ull, 0ull}};

    const float4* ag = reinterpret_cast<const float4*>(g_agg + (size_t)node * 256);
#pragma unroll 4
    for (int u = 0; u < 32; u++) {
        float4 Aq = ag[u * 2 + 0];
        float4 Bq = ag[u * 2 + 1];
#pragma unroll
        for (int half = 0; half < 2; half++) {
            int k = half * 32 + u;
            ulonglong2 ws = *(const ulonglong2*)&sW2s[k * 32 + wo];
            ulonglong2 wv = *(const ulonglong2*)&sW2v[k * 32 + wo];
            float as  = half ? Aq.y : Aq.x;
            float avx = half ? Bq.y : Aq.z;
            float avy = half ? Bq.z : Aq.w;
            float avz = half ? Bq.w : Bq.x;
            unsigned long long as2  = pack2(as, as);
            unsigned long long avx2 = pack2(avx, avx);
            unsigned long long avy2 = pack2(avy, avy);
            unsigned long long avz2 = pack2(avz, avz);
            fma2(accs2[0], as2, ws.x);
            fma2(accs2[1], as2, ws.y);
            fma2(accv2[0][0], avx2, wv.x);
            fma2(accv2[0][1], avx2, wv.y);
            fma2(accv2[1][0], avy2, wv.x);
            fma2(accv2[1][1], avy2, wv.y);
            fma2(accv2[2][0], avz2, wv.x);
            fma2(accv2[2][1], avz2, wv.y);
        }
    }

    unsigned long long at2[8];
    const float* arow = attrs + node * 8;
#pragma unroll
    for (int v = 0; v < 8; v++) { float a = arow[v]; at2[v] = pack2(a, a); }

    const float* srow = node_s + node * 32;
    const float* vrow = node_v + node * 96;
#pragma unroll 2
    for (int u = 0; u < 32; u++) {
        float su = srow[u];
        float vx = vrow[u * 3 + 0], vy = vrow[u * 3 + 1], vz = vrow[u * 3 + 2];
        unsigned long long Ts[2] = {0ull, 0ull};
        unsigned long long Tv[2] = {0ull, 0ull};
#pragma unroll
        for (int v = 0; v < 8; v++) {
            ulonglong2 ps = *(const ulonglong2*)&sWscs[(u * 8 + v) * 32 + wo];
            ulonglong2 pv = *(const ulonglong2*)&sWscv[(u * 8 + v) * 32 + wo];
            fma2(Ts[0], at2[v], ps.x);
            fma2(Ts[1], at2[v], ps.y);
            fma2(Tv[0], at2[v], pv.x);
            fma2(Tv[1], at2[v], pv.y);
        }
        unsigned long long su2 = pack2(su, su);
        unsigned long long vx2 = pack2(vx, vx);
        unsigned long long vy2 = pack2(vy, vy);
        unsigned long long vz2 = pack2(vz, vz);
#pragma unroll
        for (int p = 0; p < 2; p++) {
            fma2(accs2[p], su2, Ts[p]);
            fma2(accv2[0][p], vx2, Tv[p]);
            fma2(accv2[1][p], vy2, Tv[p]);
            fma2(accv2[2][p], vz2, Tv[p]);
        }
    }

    float* o = out + (size_t)node * 128;
#pragma unroll
    for (int p = 0; p < 2; p++) {
        float s0, s1;
        unpack2(s0, s1, accs2[p]);
        float v0[3], v1[3];
        unpack2(v0[0], v1[0], accv2[0][p]);
        unpack2(v0[1], v1[1], accv2[1][p]);
        unpack2(v0[2], v1[2], accv2[2][p]);
        int w0 = wo + p * 2;
        o[w0]     = s0;
        o[w0 + 1] = s1;
        o[32 + w0 * 3 + 0] = v0[0];
        o[32 + w0 * 3 + 1] = v0[1];
        o[32 + w0 * 3 + 2] = v0[2];
        o[32 + (w0 + 1) * 3 + 0] = v1[0];
        o[32 + (w0 + 1) * 3 + 1] = v1[1];
        o[32 + (w0 + 1) * 3 + 2] = v1[2];
    }
}

// ---------------------------------------------------------------------------
extern "C" void kernel_launch(void* const* d_in, const int* in_sizes, int n_in,
                              void* d_out, int out_size) {
    const float* node_s     = (const float*)d_in[0];
    const float* node_v     = (const float*)d_in[1];
    const float* node_attrs = (const float*)d_in[2];
    const float* edge_emb   = (const float*)d_in[3];
    const float* edge_y0    = (const float*)d_in[4];
    const float* edge_y1    = (const float*)d_in[5];
    const int*   edge_index = (const int*)d_in[6];
    const float* W1s        = (const float*)d_in[7];
    const float* W1v        = (const float*)d_in[8];
    const float* Wr1        = (const float*)d_in[9];
    const float* Wr2        = (const float*)d_in[10];
    const float* W2s        = (const float*)d_in[11];
    const float* W2v        = (const float*)d_in[12];
    const float* Wscs       = (const float*)d_in[13];
    const float* Wscv       = (const float*)d_in[14];
    float* out = (float*)d_out;

    cudaFuncSetAttribute(k_edge, cudaFuncAttributeMaxDynamicSharedMemorySize,
                         EDGE_SMEM_FLOATS * sizeof(float));
    cudaFuncSetAttribute(k_out, cudaFuncAttributeMaxDynamicSharedMemorySize,
                         OUT_SMEM_FLOATS * sizeof(float));

    k_zero<<<5000, 256>>>();
    k_hist<<<2500, 256>>>(edge_index);
    k_scan<<<1, 1024>>>();
    k_scatter<<<2500, 256>>>(edge_index);
    k_lin1<<<(2 * N_NODES + 255) / 256, 256>>>(node_s, node_v, W1s, W1v);
    k_edge<<<N_EDGES / ET, 256, EDGE_SMEM_FLOATS * sizeof(float)>>>(
        edge_emb, edge_y0, edge_y1, edge_index, Wr1, Wr2);
    k_out<<<(N_NODES * 8) / 256, 256, OUT_SMEM_FLOATS * sizeof(float)>>>(
        node_s, node_v, node_attrs, W2s, W2v, Wscs, Wscv, out);
}